// round 14
// baseline (speedup 1.0000x reference)
#include <cuda_runtime.h>
#include <cuda_bf16.h>
#include <cstdint>

// Problem constants (Query2Context_15539191677614)
#define T_LEN 16384
#define J_LEN 64
#define D_LEN 1024
#define GRIDM 512            // reader blocks: 32 rows each (512*32 = 16384)
#define ROWS_PB 32
#define COLH 512             // column half (floats)
#define COLH4 128            // column half (float4)

// Scratch (no cudaMalloc; overwritten every replay -> deterministic)
__device__ float g_e[T_LEN];                // exp(rowmax) per row
__device__ float g_bsum[GRIDM];             // per-reader-block exp sums
__device__ float g_partialA[GRIDM * COLH];  // partials for k in [0,512)
__device__ float g_partialB[GRIDM * COLH];  // partials for k in [512,1024)

__device__ __forceinline__ uint32_t smem_u32(const void* p) {
    uint32_t a;
    asm("{ .reg .u64 t; cvta.to.shared.u64 t, %1; cvt.u32.u64 %0, t; }"
        : "=r"(a) : "l"(p));
    return a;
}

// ---------------------------------------------------------------------------
// Reader body: block br owns rows [32*br, 32*br+32), streams column half
// (col4_off = 0 or 128 in float4 units) of h, produces 512 partials.
// e_sh must hold the 32 exp values for these rows on entry.
// ---------------------------------------------------------------------------
__device__ __forceinline__ void reader_phaseC(
    const float* __restrict__ h, int br, int col4_off,
    const float* e_sh, float4 (*red)[COLH4], float* __restrict__ partial_out)
{
    const int tid = threadIdx.x;
    const int g   = tid >> 7;          // row-in-quad 0..3
    const int c4  = tid & 127;         // float4 column within half
    const int t0  = br * ROWS_PB;

    float4 acc = make_float4(0.f, 0.f, 0.f, 0.f);
    const float4* __restrict__ hp = reinterpret_cast<const float4*>(h)
        + (size_t)(t0 + g) * (D_LEN / 4) + col4_off + c4;
    #pragma unroll
    for (int i = 0; i < 8; i++) {      // 8 quads x 4 rows = 32 rows
        const float4 v = __ldcs(hp + (size_t)i * D_LEN);  // 4 rows = 1024 f4
        const float  e = e_sh[4 * i + g];
        acc.x = fmaf(e, v.x, acc.x);
        acc.y = fmaf(e, v.y, acc.y);
        acc.z = fmaf(e, v.z, acc.z);
        acc.w = fmaf(e, v.w, acc.w);
    }
    red[g][c4] = acc;
    __syncthreads();

    // Reduce across the 4 row-groups; thread owns local column kk = tid
    const int k4   = tid >> 2;
    const int comp = tid & 3;
    const float* rp = reinterpret_cast<const float*>(&red[0][k4]) + comp;
    partial_out[(size_t)br * COLH + tid] = rp[0] + rp[512] + rp[1024] + rp[1536];
}

// ---------------------------------------------------------------------------
// Writer body: gather 512 partials + 512 bsums, tree reduce, v = ctx/S,
// fill 16KB smem tile, TMA bulk-store out[k, 0..T) = 64KB.
// ---------------------------------------------------------------------------
__device__ __forceinline__ void writer_body(
    float* __restrict__ out, int k, const float* __restrict__ partial, int kk)
{
    __shared__ float shp[512];
    __shared__ float shs[512];
    __shared__ __align__(128) float4 buf[1024];   // 16KB broadcast tile

    const int tid = threadIdx.x;

    shp[tid] = partial[(size_t)tid * COLH + kk];
    shs[tid] = g_bsum[tid];
    __syncthreads();

    #pragma unroll
    for (int off = 256; off > 0; off >>= 1) {
        if (tid < off) {
            shp[tid] += shp[tid + off];
            shs[tid] += shs[tid + off];
        }
        __syncthreads();
    }

    const float v = shp[0] / shs[0];
    const float4 vv = make_float4(v, v, v, v);
    buf[tid]       = vv;
    buf[tid + 512] = vv;                 // 1024 * 16B = 16KB
    __syncthreads();
    asm volatile("fence.proxy.async.shared::cta;" ::: "memory");

    if (tid == 0) {
        const uint32_t src = smem_u32(buf);
        float* row = out + (size_t)k * T_LEN;   // 64KB per output row
        #pragma unroll
        for (int c = 0; c < 4; c++) {
            asm volatile(
                "cp.async.bulk.global.shared::cta.bulk_group [%0], [%1], %2;"
                :: "l"(row + c * 4096), "r"(src), "n"(16384)
                : "memory");
        }
        asm volatile("cp.async.bulk.commit_group;" ::: "memory");
        asm volatile("cp.async.bulk.wait_group 0;" ::: "memory");
    }
}

// ---------------------------------------------------------------------------
// Kernel A: rowmax/exp for all rows + column-half-A partials.
// ---------------------------------------------------------------------------
__global__ __launch_bounds__(512)
void k_A(const float* __restrict__ h, const float* __restrict__ s) {
    __shared__ float  e_sh[ROWS_PB];
    __shared__ float4 red[4][COLH4];   // 8KB

    const int br   = blockIdx.x;
    const int t0   = br * ROWS_PB;
    const int tid  = threadIdx.x;
    const int w    = tid >> 5;         // 16 warps
    const int lane = tid & 31;

    // Phase A: warp-per-row max over J=64 (lane reads float2 -> 256B/row)
    for (int r = w; r < ROWS_PB; r += 16) {
        const float2 v = __ldcs(reinterpret_cast<const float2*>(
            s + (size_t)(t0 + r) * J_LEN) + lane);
        float m = fmaxf(v.x, v.y);
        #pragma unroll
        for (int off = 16; off > 0; off >>= 1)
            m = fmaxf(m, __shfl_xor_sync(0xFFFFFFFFu, m, off));
        if (lane == 0) e_sh[r] = expf(m);
    }
    __syncthreads();

    // Phase B: warp 0 -> g_bsum[br] and spill e to gmem for k_mid readers
    if (w == 0) {
        const float e = e_sh[lane];    // 32 rows, one per lane
        g_e[t0 + lane] = e;
        float bs = e;
        #pragma unroll
        for (int off = 16; off > 0; off >>= 1)
            bs += __shfl_xor_sync(0xFFFFFFFFu, bs, off);
        if (lane == 0) g_bsum[br] = bs;
    }
    __syncthreads();

    // Phase C: column half A
    reader_phaseC(h, br, /*col4_off=*/0, e_sh, red, g_partialA);
}

// ---------------------------------------------------------------------------
// Kernel MID (block-specialized): even blocks WRITE out rows [0,512),
// odd blocks READ column-half-B of h -> partialsB. The two groups run
// concurrently, overlapping the DRAM read path with the store path.
// ---------------------------------------------------------------------------
__global__ __launch_bounds__(512)
void k_mid(const float* __restrict__ h, float* __restrict__ out) {
    const int idx = blockIdx.x >> 1;
    if ((blockIdx.x & 1) == 0) {
        // Writer: output row k = idx in [0,512)
        writer_body(out, idx, g_partialA, idx);
    } else {
        // Reader: block br = idx, column half B
        __shared__ float  e_sh[ROWS_PB];
        __shared__ float4 red[4][COLH4];
        const int tid = threadIdx.x;
        if (tid < ROWS_PB) e_sh[tid] = g_e[idx * ROWS_PB + tid];
        __syncthreads();
        reader_phaseC(h, idx, /*col4_off=*/COLH4, e_sh, red, g_partialB);
    }
}

// ---------------------------------------------------------------------------
// Kernel C: write out rows [512,1024) from partialsB.
// ---------------------------------------------------------------------------
__global__ __launch_bounds__(512)
void k_C(float* __restrict__ out) {
    writer_body(out, 512 + blockIdx.x, g_partialB, blockIdx.x);
}

// ---------------------------------------------------------------------------
extern "C" void kernel_launch(void* const* d_in, const int* in_sizes, int n_in,
                              void* d_out, int out_size) {
    const float* h = (const float*)d_in[0];   // [1, T, d]
    const float* s = (const float*)d_in[1];   // [T, J]
    float* out = (float*)d_out;               // [d, T]

    k_A  <<<GRIDM,      512>>>(h, s);
    k_mid<<<GRIDM * 2,  512>>>(h, out);
    k_C  <<<COLH,       512>>>(out);
}